// round 1
// baseline (speedup 1.0000x reference)
#include <cuda_runtime.h>
#include <math.h>

#define KS 64
#define KM 16
#define TWO_PI 6.28318530717958647692f

// Spline knot tables, computed once per launch by prep kernel.
__device__ float gXK[KS + 1];
__device__ float gYK[KS + 1];
__device__ float gDV[KS + 1];

// ---------------------------------------------------------------------------
// Prologue: softmax+cumsum for knots, softplus for derivatives. Tiny; runs
// once per graph replay. 64 threads, thread 0 does the serial cumsums.
// ---------------------------------------------------------------------------
__global__ void spline_prep_kernel(const float* __restrict__ tw,
                                   const float* __restrict__ th,
                                   const float* __restrict__ td) {
    __shared__ float ew[KS];
    __shared__ float eh[KS];
    int t = threadIdx.x;
    if (t < KS) {
        ew[t] = tw[t];
        eh[t] = th[t];
    }
    __syncthreads();
    if (t == 0) {
        float mw = ew[0], mh = eh[0];
        #pragma unroll 8
        for (int i = 1; i < KS; i++) {
            mw = fmaxf(mw, ew[i]);
            mh = fmaxf(mh, eh[i]);
        }
        float sw = 0.f, sh = 0.f;
        #pragma unroll 8
        for (int i = 0; i < KS; i++) {
            ew[i] = expf(ew[i] - mw); sw += ew[i];
            eh[i] = expf(eh[i] - mh); sh += eh[i];
        }
        float isw = 1.f / sw, ish = 1.f / sh;
        float cw = 0.f, ch = 0.f;
        gXK[0] = -1.0f;
        gYK[0] = -1.0f;
        for (int i = 0; i < KS; i++) {
            cw += ew[i] * isw * 2.0f;   // width_i, then running cumsum
            ch += eh[i] * ish * 2.0f;
            gXK[i + 1] = cw - 1.0f;
            gYK[i + 1] = ch - 1.0f;
        }
        gDV[0] = 1.0f;
        gDV[KS] = 1.0f;
        #pragma unroll 8
        for (int i = 0; i < KS - 1; i++) {
            float x = td[i];
            // softplus(x) = max(x,0) + log1p(exp(-|x|))
            gDV[i + 1] = fmaxf(x, 0.f) + log1pf(expf(-fabsf(x))) + 0.001f;
        }
    }
}

// ---------------------------------------------------------------------------
// Main fused kernel: spline + MLP + Mobius, one thread per point.
// ---------------------------------------------------------------------------
#define TPB 128

__global__ void __launch_bounds__(TPB)
mobius_spline_kernel(const float* __restrict__ R,
                     const float* __restrict__ Z,
                     const float* __restrict__ W1,
                     const float* __restrict__ b1,
                     const float* __restrict__ W2,
                     const float* __restrict__ b2,
                     const float* __restrict__ W3,
                     const float* __restrict__ b3,
                     float* __restrict__ out,
                     int N) {
    __shared__ float sW2[64 * 64];   // 16 KB
    __shared__ float sW3[64 * 48];   // 12 KB
    __shared__ float sW1[64], sb1[64], sb2[64], sb3[48];
    __shared__ float sxk[KS + 1], syk[KS + 1], sdv[KS + 1];

    int tid = threadIdx.x;
    for (int i = tid; i < 64 * 64; i += TPB) sW2[i] = W2[i];
    for (int i = tid; i < 64 * 48; i += TPB) sW3[i] = W3[i];
    if (tid < 64) {
        sW1[tid] = W1[tid];
        sb1[tid] = b1[tid];
        sb2[tid] = b2[tid];
    }
    if (tid < 48) sb3[tid] = b3[tid];
    if (tid < KS + 1) {
        sxk[tid] = gXK[tid];
        syk[tid] = gYK[tid];
        sdv[tid] = gDV[tid];
    }
    __syncthreads();

    int idx = blockIdx.x * TPB + tid;
    if (idx >= N) return;

    float r = R[idx];
    float x = Z[idx];

    // ---------------- Rational-quadratic spline on r ----------------
    int lo = 0, hi = KS + 1;
    while (lo < hi) {                       // searchsorted, side='left'
        int mid = (lo + hi) >> 1;
        if (sxk[mid] < r) lo = mid + 1; else hi = mid;
    }
    int k = lo;
    if (k == 0) k = 1;
    if (k == KS + 1) k = KS;
    k -= 1;

    float xk = sxk[k], xn = sxk[k + 1];
    float yk = syk[k], yn = syk[k + 1];
    float dk = sdv[k], dnk = sdv[k + 1];
    float invw = 1.0f / (xn - xk);
    float s_k  = (yn - yk) * invw;
    float eps  = (r - xk) * invw;
    float ome  = 1.0f - eps;
    float eom  = eps * ome;
    float den  = s_k + (dnk + dk - 2.0f * s_k) * eom;
    float tr   = yk + (yn - yk) * (s_k * eps * eps + dk * eom) / den;
    float dtr  = s_k * s_k * (dnk * eps * eps + 2.0f * s_k * eom + dk * ome * ome)
                 / (den * den);

    // ---------------- MLP: 1 -> 64 -> 64 -> 48 ----------------
    float h1[64];
    #pragma unroll
    for (int i = 0; i < 64; i++)
        h1[i] = fmaxf(fmaf(r, sW1[i], sb1[i]), 0.0f);

    float th[48];
    #pragma unroll
    for (int t = 0; t < 48; t++) th[t] = sb3[t];

    for (int j = 0; j < 64; j++) {
        float a0 = sb2[j], a1 = 0.f, a2 = 0.f, a3 = 0.f;
        #pragma unroll
        for (int i = 0; i < 64; i += 4) {
            a0 = fmaf(h1[i + 0], sW2[(i + 0) * 64 + j], a0);
            a1 = fmaf(h1[i + 1], sW2[(i + 1) * 64 + j], a1);
            a2 = fmaf(h1[i + 2], sW2[(i + 2) * 64 + j], a2);
            a3 = fmaf(h1[i + 3], sW2[(i + 3) * 64 + j], a3);
        }
        float h2 = fmaxf((a0 + a1) + (a2 + a3), 0.0f);
        const float* w3r = &sW3[j * 48];
        #pragma unroll
        for (int t = 0; t < 48; t++)
            th[t] = fmaf(h2, w3r[t], th[t]);
    }

    // ---------------- Mobius transform on z ----------------
    // softmax over th[0..15]
    float mx = th[0];
    #pragma unroll
    for (int t = 1; t < KM; t++) mx = fmaxf(mx, th[t]);
    float se = 0.f;
    #pragma unroll
    for (int t = 0; t < KM; t++) {
        th[t] = expf(th[t] - mx);
        se += th[t];
    }
    float inv_se = 1.0f / se;

    float sx, cx;
    sincosf(x, &sx, &cx);           // zv = (cos x, sin x)

    float t_acc = 0.f, dt_acc = 0.f;
    #pragma unroll
    for (int kk = 0; kk < KM; kk++) {
        float wa = th[KM + 2 * kk];
        float wb = th[KM + 2 * kk + 1];
        float nr = sqrtf(wa * wa + wb * wb);
        float s  = 0.99f / (1.0f + nr);
        float wx = s * wa, wy = s * wb;
        float wn2 = wx * wx + wy * wy;

        // h_map(zv, w)
        float dx = cx - wx, dy = sx - wy;
        float dn2 = dx * dx + dy * dy;
        float c   = (1.0f - wn2) / dn2;
        float hzx = fmaf(c, dx, -wx);
        float hzy = fmaf(c, dy, -wy);

        // h_map((1,0), w)
        float ex = 1.0f - wx, ey = -wy;
        float en2 = ex * ex + ey * ey;
        float c0  = (1.0f - wn2) / en2;
        float h0x = fmaf(c0, ex, -wx);
        float h0y = fmaf(c0, ey, -wy);

        float txv = atan2f(hzy, hzx) - atan2f(h0y, h0x);
        if (txv < 0.0f) txv += TWO_PI;

        float wgt = th[kk] * inv_se;
        t_acc  = fmaf(wgt, txv, t_acc);
        // |dh| == c exactly: dz - 2u(u.dz) is a reflection of the unit dz.
        dt_acc = fmaf(wgt, c, dt_acc);
    }

    out[idx]         = tr;
    out[N + idx]     = t_acc;
    out[2 * N + idx] = logf(dtr) + logf(dt_acc);
}

// ---------------------------------------------------------------------------
extern "C" void kernel_launch(void* const* d_in, const int* in_sizes, int n_in,
                              void* d_out, int out_size) {
    const float* r  = (const float*)d_in[0];
    const float* z  = (const float*)d_in[1];
    const float* tw = (const float*)d_in[2];
    const float* th = (const float*)d_in[3];
    const float* td = (const float*)d_in[4];
    const float* W1 = (const float*)d_in[5];
    const float* b1 = (const float*)d_in[6];
    const float* W2 = (const float*)d_in[7];
    const float* b2 = (const float*)d_in[8];
    const float* W3 = (const float*)d_in[9];
    const float* b3 = (const float*)d_in[10];
    float* out = (float*)d_out;
    int N = in_sizes[0];

    spline_prep_kernel<<<1, 64>>>(tw, th, td);
    int grid = (N + TPB - 1) / TPB;
    mobius_spline_kernel<<<grid, TPB>>>(r, z, W1, b1, W2, b2, W3, b3, out, N);
}

// round 2
// speedup vs baseline: 3.0792x; 3.0792x over previous
#include <cuda_runtime.h>
#include <math.h>

#define KS 64
#define KM 16
#define TWO_PI 6.28318530717958647692f
#define TPB 128

typedef unsigned long long ull;

// Spline knot tables + transposed W2, computed once per replay by prep kernel.
__device__ float gXK[KS + 1];
__device__ float gYK[KS + 1];
__device__ float gDV[KS + 1];
__device__ float gW2t[64 * 64];   // gW2t[j*64+i] = W2[i*64+j]

// ---------------- packed f32x2 helpers (Blackwell) ----------------
__device__ __forceinline__ ull pk2(float a, float b) {
    ull r; asm("mov.b64 %0, {%1,%2};" : "=l"(r) : "f"(a), "f"(b)); return r;
}
__device__ __forceinline__ void upk2(ull v, float& a, float& b) {
    asm("mov.b64 {%0,%1}, %2;" : "=f"(a), "=f"(b) : "l"(v));
}
#define FMA_X2(d, a, b, c) \
    asm("fma.rn.f32x2 %0, %1, %2, %3;" : "=l"(d) : "l"(a), "l"(b), "l"(c))
#define ADD_X2(d, a, b) \
    asm("add.rn.f32x2 %0, %1, %2;" : "=l"(d) : "l"(a), "l"(b))

// ---------------------------------------------------------------------------
// Prologue: spline tables + W2 transpose. Tiny.
// ---------------------------------------------------------------------------
__global__ void spline_prep_kernel(const float* __restrict__ tw,
                                   const float* __restrict__ th,
                                   const float* __restrict__ td,
                                   const float* __restrict__ W2) {
    __shared__ float ew[KS];
    __shared__ float eh[KS];
    int t = threadIdx.x;

    // transpose W2 -> gW2t
    for (int idx = t; idx < 64 * 64; idx += blockDim.x) {
        int j = idx >> 6, i = idx & 63;
        gW2t[idx] = W2[i * 64 + j];
    }

    if (t < KS) { ew[t] = tw[t]; eh[t] = th[t]; }
    __syncthreads();
    if (t == 0) {
        float mw = ew[0], mh = eh[0];
        for (int i = 1; i < KS; i++) { mw = fmaxf(mw, ew[i]); mh = fmaxf(mh, eh[i]); }
        float sw = 0.f, sh = 0.f;
        for (int i = 0; i < KS; i++) {
            ew[i] = expf(ew[i] - mw); sw += ew[i];
            eh[i] = expf(eh[i] - mh); sh += eh[i];
        }
        float isw = 1.f / sw, ish = 1.f / sh;
        float cw = 0.f, ch = 0.f;
        gXK[0] = -1.0f; gYK[0] = -1.0f;
        for (int i = 0; i < KS; i++) {
            cw += ew[i] * isw * 2.0f;
            ch += eh[i] * ish * 2.0f;
            gXK[i + 1] = cw - 1.0f;
            gYK[i + 1] = ch - 1.0f;
        }
        gDV[0] = 1.0f; gDV[KS] = 1.0f;
        for (int i = 0; i < KS - 1; i++) {
            float x = td[i];
            gDV[i + 1] = fmaxf(x, 0.f) + log1pf(expf(-fabsf(x))) + 0.001f;
        }
    }
}

// ---------------------------------------------------------------------------
// Main fused kernel: spline + MLP (packed f32x2) + Mobius, one thread/point.
// ---------------------------------------------------------------------------
__global__ void __launch_bounds__(TPB)
mobius_spline_kernel(const float* __restrict__ R,
                     const float* __restrict__ Z,
                     const float* __restrict__ W1,
                     const float* __restrict__ b1,
                     const float* __restrict__ b2,
                     const float* __restrict__ W3,
                     const float* __restrict__ b3,
                     float* __restrict__ out,
                     int N) {
    __shared__ __align__(16) float sW2t[64 * 64];  // 16 KB, row j contiguous in i
    __shared__ __align__(16) float sW3[64 * 48];   // 12 KB, row j contiguous in t
    __shared__ __align__(16) float sW1[64];
    __shared__ __align__(16) float sb1[64];
    __shared__ __align__(16) float sb2[64];
    __shared__ __align__(16) float sb3[48];
    __shared__ float sxk[KS + 1], syk[KS + 1], sdv[KS + 1];

    int tid = threadIdx.x;
    for (int i = tid; i < 64 * 64; i += TPB) sW2t[i] = gW2t[i];
    for (int i = tid; i < 64 * 48; i += TPB) sW3[i] = W3[i];
    if (tid < 64) { sW1[tid] = W1[tid]; sb1[tid] = b1[tid]; sb2[tid] = b2[tid]; }
    if (tid < 48) sb3[tid] = b3[tid];
    if (tid < KS + 1) { sxk[tid] = gXK[tid]; syk[tid] = gYK[tid]; sdv[tid] = gDV[tid]; }
    __syncthreads();

    int idx = blockIdx.x * TPB + tid;
    if (idx >= N) return;

    float r = R[idx];
    float x = Z[idx];

    // ---------------- Rational-quadratic spline on r ----------------
    int lo = 0, hi = KS + 1;
    while (lo < hi) {
        int mid = (lo + hi) >> 1;
        if (sxk[mid] < r) lo = mid + 1; else hi = mid;
    }
    int k = lo;
    if (k == 0) k = 1;
    if (k == KS + 1) k = KS;
    k -= 1;

    float xk = sxk[k], xn = sxk[k + 1];
    float yk = syk[k], yn = syk[k + 1];
    float dk = sdv[k], dnk = sdv[k + 1];
    float invw = 1.0f / (xn - xk);
    float s_k  = (yn - yk) * invw;
    float eps  = (r - xk) * invw;
    float ome  = 1.0f - eps;
    float eom  = eps * ome;
    float den  = s_k + (dnk + dk - 2.0f * s_k) * eom;
    float tr   = yk + (yn - yk) * (s_k * eps * eps + dk * eom) / den;
    float dtr  = s_k * s_k * (dnk * eps * eps + 2.0f * s_k * eom + dk * ome * ome)
                 / (den * den);

    // ---------------- MLP: 1 -> 64 -> 64 -> 48 (packed f32x2) ----------------
    // h1 as 32 packed pairs
    ull h1p[32];
    #pragma unroll
    for (int i2 = 0; i2 < 32; i2++) {
        float a = fmaxf(fmaf(r, sW1[2 * i2],     sb1[2 * i2]),     0.0f);
        float b = fmaxf(fmaf(r, sW1[2 * i2 + 1], sb1[2 * i2 + 1]), 0.0f);
        h1p[i2] = pk2(a, b);
    }

    // th accumulators: 24 packed pairs, init from b3
    ull thp[24];
    const ull* b3p = (const ull*)sb3;
    #pragma unroll
    for (int t2 = 0; t2 < 24; t2++) thp[t2] = b3p[t2];

    for (int j = 0; j < 64; j++) {
        // h2_j = relu(b2_j + sum_i h1[i] * W2t[j][i])
        const ulonglong2* w2q = (const ulonglong2*)&sW2t[j * 64];
        ull a0 = 0ULL, a1 = 0ULL, a2 = 0ULL, a3 = 0ULL;
        #pragma unroll
        for (int q = 0; q < 8; q++) {
            ulonglong2 va = w2q[2 * q];
            ulonglong2 vb = w2q[2 * q + 1];
            FMA_X2(a0, h1p[4 * q + 0], va.x, a0);
            FMA_X2(a1, h1p[4 * q + 1], va.y, a1);
            FMA_X2(a2, h1p[4 * q + 2], vb.x, a2);
            FMA_X2(a3, h1p[4 * q + 3], vb.y, a3);
        }
        ADD_X2(a0, a0, a1);
        ADD_X2(a2, a2, a3);
        ADD_X2(a0, a0, a2);
        float s0, s1;
        upk2(a0, s0, s1);
        float h2 = fmaxf((s0 + s1) + sb2[j], 0.0f);
        ull h2p = pk2(h2, h2);

        // th += h2 * W3[j][:]
        const ulonglong2* w3q = (const ulonglong2*)&sW3[j * 48];
        #pragma unroll
        for (int q = 0; q < 12; q++) {
            ulonglong2 v = w3q[q];
            FMA_X2(thp[2 * q + 0], h2p, v.x, thp[2 * q + 0]);
            FMA_X2(thp[2 * q + 1], h2p, v.y, thp[2 * q + 1]);
        }
    }

    // unpack th
    float th[48];
    #pragma unroll
    for (int t2 = 0; t2 < 24; t2++) upk2(thp[t2], th[2 * t2], th[2 * t2 + 1]);

    // ---------------- Mobius transform on z ----------------
    float mx = th[0];
    #pragma unroll
    for (int t = 1; t < KM; t++) mx = fmaxf(mx, th[t]);
    float se = 0.f;
    #pragma unroll
    for (int t = 0; t < KM; t++) {
        th[t] = expf(th[t] - mx);
        se += th[t];
    }
    float inv_se = 1.0f / se;

    float sx, cx;
    sincosf(x, &sx, &cx);

    float t_acc = 0.f, dt_acc = 0.f;
    #pragma unroll
    for (int kk = 0; kk < KM; kk++) {
        float wa = th[KM + 2 * kk];
        float wb = th[KM + 2 * kk + 1];
        float nr = sqrtf(wa * wa + wb * wb);
        float s  = 0.99f / (1.0f + nr);
        float wx = s * wa, wy = s * wb;
        float wn2 = wx * wx + wy * wy;

        // h_map(zv, w)
        float dx = cx - wx, dy = sx - wy;
        float dn2 = dx * dx + dy * dy;
        float c   = (1.0f - wn2) / dn2;
        float hzx = fmaf(c, dx, -wx);
        float hzy = fmaf(c, dy, -wy);

        // h_map((1,0), w)
        float ex = 1.0f - wx, ey = -wy;
        float en2 = ex * ex + ey * ey;
        float c0  = (1.0f - wn2) / en2;
        float h0x = fmaf(c0, ex, -wx);
        float h0y = fmaf(c0, ey, -wy);

        // angle difference via complex ratio: one atan2 instead of two.
        float cross = hzy * h0x - hzx * h0y;
        float dot   = hzx * h0x + hzy * h0y;
        float txv = atan2f(cross, dot);
        if (txv < 0.0f) txv += TWO_PI;

        float wgt = th[kk] * inv_se;
        t_acc  = fmaf(wgt, txv, t_acc);
        dt_acc = fmaf(wgt, c, dt_acc);   // |dh| == c exactly (unit reflection)
    }

    out[idx]         = tr;
    out[N + idx]     = t_acc;
    out[2 * N + idx] = logf(dtr) + logf(dt_acc);
}

// ---------------------------------------------------------------------------
extern "C" void kernel_launch(void* const* d_in, const int* in_sizes, int n_in,
                              void* d_out, int out_size) {
    const float* r  = (const float*)d_in[0];
    const float* z  = (const float*)d_in[1];
    const float* tw = (const float*)d_in[2];
    const float* th = (const float*)d_in[3];
    const float* td = (const float*)d_in[4];
    const float* W1 = (const float*)d_in[5];
    const float* b1 = (const float*)d_in[6];
    const float* W2 = (const float*)d_in[7];
    const float* b2 = (const float*)d_in[8];
    const float* W3 = (const float*)d_in[9];
    const float* b3 = (const float*)d_in[10];
    float* out = (float*)d_out;
    int N = in_sizes[0];

    spline_prep_kernel<<<1, 256>>>(tw, th, td, W2);
    int grid = (N + TPB - 1) / TPB;
    mobius_spline_kernel<<<grid, TPB>>>(r, z, W1, b1, b2, W3, b3, out, N);
}

// round 3
// speedup vs baseline: 8.0491x; 2.6140x over previous
#include <cuda_runtime.h>
#include <math.h>

#define KS 64
#define KM 16
#define TWO_PI 6.28318530717958647692f

#define G     32768          // grid intervals over [-1, 1]
#define TABW  84             // floats per table row (21 float4)

typedef unsigned long long ull;

// Spline knot tables + transposed W2 (prep stage 1).
__device__ float gXK[KS + 1];
__device__ float gYK[KS + 1];
__device__ float gDV[KS + 1];
__device__ float gW2t[64 * 64];   // gW2t[j*64+i] = W2[i*64+j]

// Mobius parameter table (prep stage 2). Row layout (float4 units):
//  [0..3]  wgt[16]   [4..7] wx[16]   [8..11] wy[16]
//  [12..15] c0x[16]  [16..19] c0y[16]
//  [20] = (tr, log(dtr), pad, pad)
__device__ __align__(16) float gTab[(G + 1) * TABW];

// ---------------- packed f32x2 helpers (Blackwell) ----------------
__device__ __forceinline__ ull pk2(float a, float b) {
    ull r; asm("mov.b64 %0, {%1,%2};" : "=l"(r) : "f"(a), "f"(b)); return r;
}
__device__ __forceinline__ void upk2(ull v, float& a, float& b) {
    asm("mov.b64 {%0,%1}, %2;" : "=f"(a), "=f"(b) : "l"(v));
}
#define FMA_X2(d, a, b, c) \
    asm("fma.rn.f32x2 %0, %1, %2, %3;" : "=l"(d) : "l"(a), "l"(b), "l"(c))
#define ADD_X2(d, a, b) \
    asm("add.rn.f32x2 %0, %1, %2;" : "=l"(d) : "l"(a), "l"(b))

// ---------------------------------------------------------------------------
// Prep stage 1: spline knot tables + W2 transpose.
// ---------------------------------------------------------------------------
__global__ void spline_prep_kernel(const float* __restrict__ tw,
                                   const float* __restrict__ th,
                                   const float* __restrict__ td,
                                   const float* __restrict__ W2) {
    __shared__ float ew[KS];
    __shared__ float eh[KS];
    int t = threadIdx.x;

    for (int idx = t; idx < 64 * 64; idx += blockDim.x) {
        int j = idx >> 6, i = idx & 63;
        gW2t[idx] = W2[i * 64 + j];
    }

    if (t < KS) { ew[t] = tw[t]; eh[t] = th[t]; }
    __syncthreads();
    if (t == 0) {
        float mw = ew[0], mh = eh[0];
        for (int i = 1; i < KS; i++) { mw = fmaxf(mw, ew[i]); mh = fmaxf(mh, eh[i]); }
        float sw = 0.f, sh = 0.f;
        for (int i = 0; i < KS; i++) {
            ew[i] = expf(ew[i] - mw); sw += ew[i];
            eh[i] = expf(eh[i] - mh); sh += eh[i];
        }
        float isw = 1.f / sw, ish = 1.f / sh;
        float cw = 0.f, ch = 0.f;
        gXK[0] = -1.0f; gYK[0] = -1.0f;
        for (int i = 0; i < KS; i++) {
            cw += ew[i] * isw * 2.0f;
            ch += eh[i] * ish * 2.0f;
            gXK[i + 1] = cw - 1.0f;
            gYK[i + 1] = ch - 1.0f;
        }
        gDV[0] = 1.0f; gDV[KS] = 1.0f;
        for (int i = 0; i < KS - 1; i++) {
            float x = td[i];
            gDV[i + 1] = fmaxf(x, 0.f) + log1pf(expf(-fabsf(x))) + 0.001f;
        }
    }
}

// ---------------------------------------------------------------------------
// Prep stage 2: evaluate spline + MLP + Mobius preprocessing on the r-grid.
// One thread per grid node; weights broadcast from shared (f32x2 path).
// ---------------------------------------------------------------------------
#define PREP_TPB 128

__global__ void __launch_bounds__(PREP_TPB)
table_prep_kernel(const float* __restrict__ W1,
                  const float* __restrict__ b1,
                  const float* __restrict__ b2,
                  const float* __restrict__ W3,
                  const float* __restrict__ b3) {
    __shared__ __align__(16) float sW2t[64 * 64];
    __shared__ __align__(16) float sW3[64 * 48];
    __shared__ __align__(16) float sW1[64];
    __shared__ __align__(16) float sb1[64];
    __shared__ __align__(16) float sb2[64];
    __shared__ __align__(16) float sb3[48];
    __shared__ float sxk[KS + 1], syk[KS + 1], sdv[KS + 1];

    int tid = threadIdx.x;
    for (int i = tid; i < 64 * 64; i += PREP_TPB) sW2t[i] = gW2t[i];
    for (int i = tid; i < 64 * 48; i += PREP_TPB) sW3[i] = W3[i];
    if (tid < 64) { sW1[tid] = W1[tid]; sb1[tid] = b1[tid]; sb2[tid] = b2[tid]; }
    if (tid < 48) sb3[tid] = b3[tid];
    if (tid < KS + 1) { sxk[tid] = gXK[tid]; syk[tid] = gYK[tid]; sdv[tid] = gDV[tid]; }
    __syncthreads();

    int g = blockIdx.x * PREP_TPB + tid;
    if (g > G) return;

    float r = -1.0f + 2.0f * (float)g / (float)G;

    // ---------------- spline ----------------
    int lo = 0, hi = KS + 1;
    while (lo < hi) {
        int mid = (lo + hi) >> 1;
        if (sxk[mid] < r) lo = mid + 1; else hi = mid;
    }
    int k = lo;
    if (k == 0) k = 1;
    if (k == KS + 1) k = KS;
    k -= 1;

    float xk = sxk[k], xn = sxk[k + 1];
    float yk = syk[k], yn = syk[k + 1];
    float dk = sdv[k], dnk = sdv[k + 1];
    float invw = 1.0f / (xn - xk);
    float s_k  = (yn - yk) * invw;
    float eps  = (r - xk) * invw;
    float ome  = 1.0f - eps;
    float eom  = eps * ome;
    float den  = s_k + (dnk + dk - 2.0f * s_k) * eom;
    float tr   = yk + (yn - yk) * (s_k * eps * eps + dk * eom) / den;
    float dtr  = s_k * s_k * (dnk * eps * eps + 2.0f * s_k * eom + dk * ome * ome)
                 / (den * den);

    // ---------------- MLP 1->64->64->48 (f32x2) ----------------
    ull h1p[32];
    #pragma unroll
    for (int i2 = 0; i2 < 32; i2++) {
        float a = fmaxf(fmaf(r, sW1[2 * i2],     sb1[2 * i2]),     0.0f);
        float b = fmaxf(fmaf(r, sW1[2 * i2 + 1], sb1[2 * i2 + 1]), 0.0f);
        h1p[i2] = pk2(a, b);
    }

    ull thp[24];
    const ull* b3p = (const ull*)sb3;
    #pragma unroll
    for (int t2 = 0; t2 < 24; t2++) thp[t2] = b3p[t2];

    for (int j = 0; j < 64; j++) {
        const ulonglong2* w2q = (const ulonglong2*)&sW2t[j * 64];
        ull a0 = 0ULL, a1 = 0ULL, a2 = 0ULL, a3 = 0ULL;
        #pragma unroll
        for (int q = 0; q < 8; q++) {
            ulonglong2 va = w2q[2 * q];
            ulonglong2 vb = w2q[2 * q + 1];
            FMA_X2(a0, h1p[4 * q + 0], va.x, a0);
            FMA_X2(a1, h1p[4 * q + 1], va.y, a1);
            FMA_X2(a2, h1p[4 * q + 2], vb.x, a2);
            FMA_X2(a3, h1p[4 * q + 3], vb.y, a3);
        }
        ADD_X2(a0, a0, a1);
        ADD_X2(a2, a2, a3);
        ADD_X2(a0, a0, a2);
        float s0, s1;
        upk2(a0, s0, s1);
        float h2 = fmaxf((s0 + s1) + sb2[j], 0.0f);
        ull h2p = pk2(h2, h2);

        const ulonglong2* w3q = (const ulonglong2*)&sW3[j * 48];
        #pragma unroll
        for (int q = 0; q < 12; q++) {
            ulonglong2 v = w3q[q];
            FMA_X2(thp[2 * q + 0], h2p, v.x, thp[2 * q + 0]);
            FMA_X2(thp[2 * q + 1], h2p, v.y, thp[2 * q + 1]);
        }
    }

    float th[48];
    #pragma unroll
    for (int t2 = 0; t2 < 24; t2++) upk2(thp[t2], th[2 * t2], th[2 * t2 + 1]);

    // ---------------- Mobius preprocessing ----------------
    float mx = th[0];
    #pragma unroll
    for (int t = 1; t < KM; t++) mx = fmaxf(mx, th[t]);
    float se = 0.f;
    #pragma unroll
    for (int t = 0; t < KM; t++) {
        th[t] = expf(th[t] - mx);
        se += th[t];
    }
    float inv_se = 1.0f / se;

    float* row = &gTab[g * TABW];
    #pragma unroll
    for (int kk = 0; kk < KM; kk++) {
        float wa = th[KM + 2 * kk];
        float wb = th[KM + 2 * kk + 1];
        float nr = sqrtf(wa * wa + wb * wb);
        float s  = 0.99f / (1.0f + nr);
        float wx = s * wa, wy = s * wb;
        float wn2 = wx * wx + wy * wy;

        // shift direction: unit vector of h_map((1,0), w)
        float ex = 1.0f - wx, ey = -wy;
        float en2 = ex * ex + ey * ey;
        float c0  = (1.0f - wn2) / en2;
        float h0x = fmaf(c0, ex, -wx);
        float h0y = fmaf(c0, ey, -wy);
        float inv = rsqrtf(h0x * h0x + h0y * h0y);

        row[kk]      = th[kk] * inv_se;   // wgt
        row[16 + kk] = wx;
        row[32 + kk] = wy;
        row[48 + kk] = h0x * inv;         // c0x
        row[64 + kk] = h0y * inv;         // c0y
    }
    row[80] = tr;
    row[81] = logf(dtr);
    row[82] = 0.f;
    row[83] = 0.f;
}

// ---------------------------------------------------------------------------
// Main kernel: table lookup + lerp + Mobius angle accumulation.
// ---------------------------------------------------------------------------
#define TPB 256

__device__ __forceinline__ float4 lerp4(float4 a, float4 b, float f) {
    float4 o;
    o.x = fmaf(f, b.x - a.x, a.x);
    o.y = fmaf(f, b.y - a.y, a.y);
    o.z = fmaf(f, b.z - a.z, a.z);
    o.w = fmaf(f, b.w - a.w, a.w);
    return o;
}

__global__ void __launch_bounds__(TPB)
mobius_lookup_kernel(const float* __restrict__ R,
                     const float* __restrict__ Z,
                     float* __restrict__ out,
                     int N) {
    int idx = blockIdx.x * TPB + threadIdx.x;
    if (idx >= N) return;

    float r = R[idx];
    float z = Z[idx];

    float u = (r + 1.0f) * ((float)G * 0.5f);
    int i = (int)floorf(u);
    i = max(0, min(G - 1, i));
    float f = u - (float)i;

    const float4* p0 = (const float4*)(&gTab[i * TABW]);
    const float4* p1 = (const float4*)(&gTab[(i + 1) * TABW]);

    float sz, cz;
    sincosf(z, &sz, &cz);

    float t_acc = 0.f, dt_acc = 0.f;

    #pragma unroll
    for (int gq = 0; gq < 4; gq++) {
        float4 wg = lerp4(p0[gq],      p1[gq],      f);
        float4 wx = lerp4(p0[4 + gq],  p1[4 + gq],  f);
        float4 wy = lerp4(p0[8 + gq],  p1[8 + gq],  f);
        float4 ax = lerp4(p0[12 + gq], p1[12 + gq], f);
        float4 ay = lerp4(p0[16 + gq], p1[16 + gq], f);

        const float* wgp = (const float*)&wg;
        const float* wxp = (const float*)&wx;
        const float* wyp = (const float*)&wy;
        const float* axp = (const float*)&ax;
        const float* ayp = (const float*)&ay;

        #pragma unroll
        for (int c4 = 0; c4 < 4; c4++) {
            float wxx = wxp[c4], wyy = wyp[c4];
            float dx = cz - wxx, dy = sz - wyy;
            float wn2 = wxx * wxx + wyy * wyy;
            float dn2 = dx * dx + dy * dy;
            float c   = (1.0f - wn2) / dn2;
            float hzx = fmaf(c, dx, -wxx);
            float hzy = fmaf(c, dy, -wyy);

            float cross = hzy * axp[c4] - hzx * ayp[c4];
            float dot   = hzx * axp[c4] + hzy * ayp[c4];
            float txv = atan2f(cross, dot);
            if (txv < 0.0f) txv += TWO_PI;

            t_acc  = fmaf(wgp[c4], txv, t_acc);
            dt_acc = fmaf(wgp[c4], c, dt_acc);
        }
    }

    float4 m0 = p0[20], m1 = p1[20];
    float tr  = fmaf(f, m1.x - m0.x, m0.x);
    float ldr = fmaf(f, m1.y - m0.y, m0.y);

    out[idx]         = tr;
    out[N + idx]     = t_acc;
    out[2 * N + idx] = ldr + logf(dt_acc);
}

// ---------------------------------------------------------------------------
extern "C" void kernel_launch(void* const* d_in, const int* in_sizes, int n_in,
                              void* d_out, int out_size) {
    const float* r  = (const float*)d_in[0];
    const float* z  = (const float*)d_in[1];
    const float* tw = (const float*)d_in[2];
    const float* th = (const float*)d_in[3];
    const float* td = (const float*)d_in[4];
    const float* W1 = (const float*)d_in[5];
    const float* b1 = (const float*)d_in[6];
    const float* W2 = (const float*)d_in[7];
    const float* b2 = (const float*)d_in[8];
    const float* W3 = (const float*)d_in[9];
    const float* b3 = (const float*)d_in[10];
    float* out = (float*)d_out;
    int N = in_sizes[0];

    spline_prep_kernel<<<1, 256>>>(tw, th, td, W2);
    table_prep_kernel<<<(G + PREP_TPB) / PREP_TPB, PREP_TPB>>>(W1, b1, b2, W3, b3);
    mobius_lookup_kernel<<<(N + TPB - 1) / TPB, TPB>>>(r, z, out, N);
}